// round 5
// baseline (speedup 1.0000x reference)
#include <cuda_runtime.h>
#include <math.h>

// Problem constants: x,y are (B=2, C=6, H=512, W=512) fp32.
// Output: (B, 1, H, W, 2) fp32 — trailing axis = radius index {r=2, r=4}.
#define BATCH 2
#define CH    6
#define HH    512
#define WW    512
#define EPSV  1e-6f

#define TX 32
#define TY 8

__device__ __forceinline__ int refl(int p, int n) {
    if (p < 0) p = -p;
    if (p >= n) p = 2 * n - 2 - p;
    return p;
}

// Cholesky (packed lower 21) in place + lower-triangular inverse into li.
__device__ __forceinline__ void chol_inv6(float a[21], float li[21]) {
    float invd[6];
#pragma unroll
    for (int j = 0; j < 6; j++) {
        float d = a[j * (j + 1) / 2 + j];
#pragma unroll
        for (int t = 0; t < j; t++) {
            float v = a[j * (j + 1) / 2 + t];
            d -= v * v;
        }
        float sq = sqrtf(d);
        float inv = 1.0f / sq;
        a[j * (j + 1) / 2 + j] = sq;
        invd[j] = inv;
#pragma unroll
        for (int i = j + 1; i < 6; i++) {
            float s = a[i * (i + 1) / 2 + j];
#pragma unroll
            for (int t = 0; t < j; t++)
                s -= a[i * (i + 1) / 2 + t] * a[j * (j + 1) / 2 + t];
            a[i * (i + 1) / 2 + j] = s * inv;
        }
    }
    // inverse of lower triangular
#pragma unroll
    for (int j = 0; j < 6; j++) {
        li[j * (j + 1) / 2 + j] = invd[j];
#pragma unroll
        for (int i = j + 1; i < 6; i++) {
            float s = 0.0f;
#pragma unroll
            for (int t = j; t < i; t++)
                s += a[i * (i + 1) / 2 + t] * li[t * (t + 1) / 2 + j];
            li[i * (i + 1) / 2 + j] = -s * invd[i];
        }
    }
}

template <int R>
__global__ __launch_bounds__(TX * TY)
void cca_kernel(const float* __restrict__ x, const float* __restrict__ y,
                float* __restrict__ out, int ridx) {
    constexpr int K = 2 * R + 1;
    constexpr int TILE_W = TX + 2 * R;
    constexpr int TILE_H = TY + 2 * R;

    __shared__ float sX[CH][TILE_H][TILE_W];
    __shared__ float sY[CH][TILE_H][TILE_W];

    const int b  = blockIdx.z;
    const int x0 = blockIdx.x * TX;
    const int y0 = blockIdx.y * TY;
    const int tid = threadIdx.y * TX + threadIdx.x;

    // Cooperative load with reflect padding resolved here.
    for (int i = tid; i < TILE_H * TILE_W; i += TX * TY) {
        int ty = i / TILE_W;
        int tx = i - ty * TILE_W;
        int gy = refl(y0 + ty - R, HH);
        int gx = refl(x0 + tx - R, WW);
        long base = ((long)b * CH) * HH * WW + (long)gy * WW + gx;
#pragma unroll
        for (int c = 0; c < CH; c++) {
            sX[c][ty][tx] = x[base + (long)c * HH * WW];
            sY[c][ty][tx] = y[base + (long)c * HH * WW];
        }
    }
    __syncthreads();

    // Per-thread window accumulation: 90 sums.
    float Sx[6], Sy[6], Sxx[21], Syy[21], Sxy[36];
#pragma unroll
    for (int i = 0; i < 6; i++) { Sx[i] = 0.f; Sy[i] = 0.f; }
#pragma unroll
    for (int i = 0; i < 21; i++) { Sxx[i] = 0.f; Syy[i] = 0.f; }
#pragma unroll
    for (int i = 0; i < 36; i++) Sxy[i] = 0.f;

    const int lr = threadIdx.y;
    const int lc = threadIdx.x;

    for (int dy = 0; dy < K; dy++) {
        for (int dx = 0; dx < K; dx++) {
            float xv[6], yv[6];
#pragma unroll
            for (int c = 0; c < 6; c++) {
                xv[c] = sX[c][lr + dy][lc + dx];
                yv[c] = sY[c][lr + dy][lc + dx];
            }
#pragma unroll
            for (int i = 0; i < 6; i++) { Sx[i] += xv[i]; Sy[i] += yv[i]; }
#pragma unroll
            for (int i = 0; i < 6; i++) {
#pragma unroll
                for (int j = 0; j <= i; j++) {
                    Sxx[i * (i + 1) / 2 + j] += xv[i] * xv[j];
                    Syy[i * (i + 1) / 2 + j] += yv[i] * yv[j];
                }
            }
#pragma unroll
            for (int i = 0; i < 6; i++) {
#pragma unroll
                for (int j = 0; j < 6; j++) {
                    Sxy[i * 6 + j] += xv[i] * yv[j];
                }
            }
        }
    }

    // Epilogue
    constexpr float ia = 1.0f / (float)(K * K);
    float mx[6], my[6];
#pragma unroll
    for (int i = 0; i < 6; i++) { mx[i] = Sx[i] * ia; my[i] = Sy[i] * ia; }

    float cxy[36];
#pragma unroll
    for (int i = 0; i < 6; i++)
#pragma unroll
        for (int j = 0; j < 6; j++)
            cxy[i * 6 + j] = Sxy[i * 6 + j] * ia - mx[i] * my[j];

    float axx[21], lxi[21];
#pragma unroll
    for (int i = 0; i < 6; i++)
#pragma unroll
        for (int j = 0; j <= i; j++)
            axx[i * (i + 1) / 2 + j] =
                Sxx[i * (i + 1) / 2 + j] * ia - mx[i] * mx[j] + (i == j ? EPSV : 0.f);
    chol_inv6(axx, lxi);

    float ayy[21], lyi[21];
#pragma unroll
    for (int i = 0; i < 6; i++)
#pragma unroll
        for (int j = 0; j <= i; j++)
            ayy[i * (i + 1) / 2 + j] =
                Syy[i * (i + 1) / 2 + j] * ia - my[i] * my[j] + (i == j ? EPSV : 0.f);
    chol_inv6(ayy, lyi);

    // diag_d = sum_{j<=d} sum_{k>=d} lxi[d][j] * cxy[j][k] * lyi[k][d]
    float acc = 0.0f;
#pragma unroll
    for (int d = 0; d < 6; d++) {
        float dv = 0.0f;
#pragma unroll
        for (int k = d; k < 6; k++) {
            float t = 0.0f;
#pragma unroll
            for (int j = 0; j <= d; j++)
                t += lxi[d * (d + 1) / 2 + j] * cxy[j * 6 + k];
            dv += t * lyi[k * (k + 1) / 2 + d];
        }
        acc += fabsf(dv);
    }
    float sim = acc * (1.0f / 6.0f);

    const int gy = y0 + lr;
    const int gx = x0 + lc;
    if (gy < HH && gx < WW) {
        out[(((long)b * HH + gy) * WW + gx) * 2 + ridx] = sim;
    }
}

extern "C" void kernel_launch(void* const* d_in, const int* in_sizes, int n_in,
                              void* d_out, int out_size) {
    const float* x = (const float*)d_in[0];
    const float* y = (const float*)d_in[1];
    float* out = (float*)d_out;

    dim3 block(TX, TY, 1);
    dim3 grid(WW / TX, HH / TY, BATCH);

    cca_kernel<2><<<grid, block>>>(x, y, out, 0);
    cca_kernel<4><<<grid, block>>>(x, y, out, 1);
}

// round 6
// speedup vs baseline: 1.5726x; 1.5726x over previous
#include <cuda_runtime.h>
#include <math.h>

// x,y: (B=2, C=6, H=512, W=512) fp32. Output: (B,1,H,W,2) fp32, trailing = radius {2,4}.
#define BATCH 2
#define CH    6
#define HH    512
#define WW    512
#define EPSV  1e-6f

#define TX     32
#define TYT    8
#define NROWS  8
#define TILE_H (TYT * NROWS)   // 64

__device__ __forceinline__ int refl(int p, int n) {
    if (p < 0) p = -p;
    if (p >= n) p = 2 * n - 2 - p;
    return p;
}

// Cholesky (packed lower 21) in place + lower-triangular inverse into li.
__device__ __forceinline__ void chol_inv6(float a[21], float li[21]) {
    float invd[6];
#pragma unroll
    for (int j = 0; j < 6; j++) {
        float d = a[j * (j + 1) / 2 + j];
#pragma unroll
        for (int t = 0; t < j; t++) {
            float v = a[j * (j + 1) / 2 + t];
            d -= v * v;
        }
        float sq = sqrtf(d);
        float inv = 1.0f / sq;
        a[j * (j + 1) / 2 + j] = sq;
        invd[j] = inv;
#pragma unroll
        for (int i = j + 1; i < 6; i++) {
            float s = a[i * (i + 1) / 2 + j];
#pragma unroll
            for (int t = 0; t < j; t++)
                s -= a[i * (i + 1) / 2 + t] * a[j * (j + 1) / 2 + t];
            a[i * (i + 1) / 2 + j] = s * inv;
        }
    }
#pragma unroll
    for (int j = 0; j < 6; j++) {
        li[j * (j + 1) / 2 + j] = invd[j];
#pragma unroll
        for (int i = j + 1; i < 6; i++) {
            float s = 0.0f;
#pragma unroll
            for (int t = j; t < i; t++)
                s += a[i * (i + 1) / 2 + t] * li[t * (t + 1) / 2 + j];
            li[i * (i + 1) / 2 + j] = -s * invd[i];
        }
    }
}

// Accumulate (or subtract) one padded row's horizontal k-window of products.
template <int K, bool SUB>
__device__ __forceinline__ void accum_row(
    const float2* __restrict__ s, int chStride, int off,
    float* __restrict__ Sx, float* __restrict__ Sy,
    float* __restrict__ Sxx, float* __restrict__ Syy, float* __restrict__ Sxy) {
#pragma unroll
    for (int dx = 0; dx < K; dx++) {
        float xv[6], yv[6];
#pragma unroll
        for (int c = 0; c < 6; c++) {
            float2 v = s[c * chStride + off + dx];
            xv[c] = v.x;
            yv[c] = v.y;
        }
#pragma unroll
        for (int i = 0; i < 6; i++) {
            if (SUB) { Sx[i] -= xv[i]; Sy[i] -= yv[i]; }
            else     { Sx[i] += xv[i]; Sy[i] += yv[i]; }
        }
#pragma unroll
        for (int i = 0; i < 6; i++) {
#pragma unroll
            for (int j = 0; j <= i; j++) {
                int t = i * (i + 1) / 2 + j;
                if (SUB) { Sxx[t] -= xv[i] * xv[j]; Syy[t] -= yv[i] * yv[j]; }
                else     { Sxx[t] += xv[i] * xv[j]; Syy[t] += yv[i] * yv[j]; }
            }
        }
#pragma unroll
        for (int i = 0; i < 6; i++) {
#pragma unroll
            for (int j = 0; j < 6; j++) {
                if (SUB) Sxy[i * 6 + j] -= xv[i] * yv[j];
                else     Sxy[i * 6 + j] += xv[i] * yv[j];
            }
        }
    }
}

template <int K>
__device__ __forceinline__ float cca_epilogue(
    const float* __restrict__ Sx, const float* __restrict__ Sy,
    const float* __restrict__ Sxx, const float* __restrict__ Syy,
    const float* __restrict__ Sxy) {
    constexpr float ia = 1.0f / (float)(K * K);
    float mx[6], my[6];
#pragma unroll
    for (int i = 0; i < 6; i++) { mx[i] = Sx[i] * ia; my[i] = Sy[i] * ia; }

    float cxy[36];
#pragma unroll
    for (int i = 0; i < 6; i++)
#pragma unroll
        for (int j = 0; j < 6; j++)
            cxy[i * 6 + j] = Sxy[i * 6 + j] * ia - mx[i] * my[j];

    float axx[21], lxi[21];
#pragma unroll
    for (int i = 0; i < 6; i++)
#pragma unroll
        for (int j = 0; j <= i; j++)
            axx[i * (i + 1) / 2 + j] =
                Sxx[i * (i + 1) / 2 + j] * ia - mx[i] * mx[j] + (i == j ? EPSV : 0.f);
    chol_inv6(axx, lxi);

    float ayy[21], lyi[21];
#pragma unroll
    for (int i = 0; i < 6; i++)
#pragma unroll
        for (int j = 0; j <= i; j++)
            ayy[i * (i + 1) / 2 + j] =
                Syy[i * (i + 1) / 2 + j] * ia - my[i] * my[j] + (i == j ? EPSV : 0.f);
    chol_inv6(ayy, lyi);

    float acc = 0.0f;
#pragma unroll
    for (int d = 0; d < 6; d++) {
        float dv = 0.0f;
#pragma unroll
        for (int k = d; k < 6; k++) {
            float t = 0.0f;
#pragma unroll
            for (int j = 0; j <= d; j++)
                t += lxi[d * (d + 1) / 2 + j] * cxy[j * 6 + k];
            dv += t * lyi[k * (k + 1) / 2 + d];
        }
        acc += fabsf(dv);
    }
    return acc * (1.0f / 6.0f);
}

template <int R>
__global__ __launch_bounds__(TX * TYT, 1)
void cca_kernel(const float* __restrict__ x, const float* __restrict__ y,
                float* __restrict__ out, int ridx) {
    constexpr int K  = 2 * R + 1;
    constexpr int PW = TX + 2 * R;
    constexpr int PH = TILE_H + 2 * R;
    constexpr int CS = PH * PW;            // per-channel smem stride (float2)

    extern __shared__ float2 sData[];      // [CH][PH][PW], .x = x-input, .y = y-input

    const int b  = blockIdx.z;
    const int x0 = blockIdx.x * TX;
    const int y0 = blockIdx.y * TILE_H;
    const int tid = threadIdx.y * TX + threadIdx.x;

    // Cooperative load with reflect padding resolved at load.
    for (int i = tid; i < CS; i += TX * TYT) {
        int ty = i / PW;
        int tx = i - ty * PW;
        int gy = refl(y0 + ty - R, HH);
        int gx = refl(x0 + tx - R, WW);
        long base = ((long)b * CH) * HH * WW + (long)gy * WW + gx;
#pragma unroll
        for (int c = 0; c < CH; c++) {
            long g = base + (long)c * HH * WW;
            sData[c * CS + i] = make_float2(x[g], y[g]);
        }
    }
    __syncthreads();

    float Sx[6], Sy[6], Sxx[21], Syy[21], Sxy[36];
#pragma unroll
    for (int i = 0; i < 6; i++) { Sx[i] = 0.f; Sy[i] = 0.f; }
#pragma unroll
    for (int i = 0; i < 21; i++) { Sxx[i] = 0.f; Syy[i] = 0.f; }
#pragma unroll
    for (int i = 0; i < 36; i++) Sxy[i] = 0.f;

    const int tx = threadIdx.x;
    const int rb = threadIdx.y * NROWS;    // first output-local row for this thread
    const long outBase = (((long)b * HH + (y0 + rb)) * WW + (x0 + tx)) * 2 + ridx;

#pragma unroll 1
    for (int s = 0; s < NROWS; s++) {
        if (s == 0) {
            // Build initial window: K padded rows rb .. rb+K-1.
#pragma unroll 1
            for (int p = 0; p < K; p++)
                accum_row<K, false>(sData, CS, (rb + p) * PW + tx, Sx, Sy, Sxx, Syy, Sxy);
        } else {
            // Slide: subtract leaving row, add entering row.
            accum_row<K, true >(sData, CS, (rb + s - 1) * PW + tx, Sx, Sy, Sxx, Syy, Sxy);
            accum_row<K, false>(sData, CS, (rb + s - 1 + K) * PW + tx, Sx, Sy, Sxx, Syy, Sxy);
        }
        float sim = cca_epilogue<K>(Sx, Sy, Sxx, Syy, Sxy);
        out[outBase + (long)s * WW * 2] = sim;
    }
}

extern "C" void kernel_launch(void* const* d_in, const int* in_sizes, int n_in,
                              void* d_out, int out_size) {
    const float* x = (const float*)d_in[0];
    const float* y = (const float*)d_in[1];
    float* out = (float*)d_out;

    const size_t smem2 = sizeof(float2) * CH * (TILE_H + 4) * (TX + 4);  // 117,504 B
    const size_t smem4 = sizeof(float2) * CH * (TILE_H + 8) * (TX + 8);  // 138,240 B
    cudaFuncSetAttribute(cca_kernel<2>, cudaFuncAttributeMaxDynamicSharedMemorySize, (int)smem2);
    cudaFuncSetAttribute(cca_kernel<4>, cudaFuncAttributeMaxDynamicSharedMemorySize, (int)smem4);

    dim3 block(TX, TYT, 1);
    dim3 grid(WW / TX, HH / TILE_H, BATCH);

    cca_kernel<2><<<grid, block, smem2>>>(x, y, out, 0);
    cca_kernel<4><<<grid, block, smem4>>>(x, y, out, 1);
}

// round 7
// speedup vs baseline: 2.2738x; 1.4459x over previous
#include <cuda_runtime.h>
#include <math.h>

// x,y: (B=2, C=6, H=512, W=512) fp32. Output: (B,1,H,W,2) fp32, trailing = radius {2,4}.
#define BATCH 2
#define CH    6
#define HH    512
#define WW    512
#define EPSV  1e-6f

#define TX     32
#define TYT    8
#define NROWS  8
#define TILE_H (TYT * NROWS)   // 64

typedef unsigned long long u64;
union PF { u64 u; float2 f; };

#define NEG1_2 0xBF800000BF800000ull   // (-1.0f, -1.0f)

__device__ __forceinline__ u64 fma2(u64 a, u64 b, u64 c) {
    u64 d; asm("fma.rn.f32x2 %0, %1, %2, %3;" : "=l"(d) : "l"(a), "l"(b), "l"(c)); return d;
}
__device__ __forceinline__ u64 add2(u64 a, u64 b) {
    u64 d; asm("add.rn.f32x2 %0, %1, %2;" : "=l"(d) : "l"(a), "l"(b)); return d;
}
__device__ __forceinline__ u64 mul2(u64 a, u64 b) {
    u64 d; asm("mul.rn.f32x2 %0, %1, %2;" : "=l"(d) : "l"(a), "l"(b)); return d;
}
__device__ __forceinline__ u64 pack2(float lo, float hi) {
    u64 d; asm("mov.b64 %0, {%1, %2};" : "=l"(d) : "f"(lo), "f"(hi)); return d;
}

__device__ __forceinline__ int refl(int p, int n) {
    if (p < 0) p = -p;
    if (p >= n) p = 2 * n - 2 - p;
    return p;
}

// Packed Cholesky (lower, packed 21) for TWO matrices at once (lo/hi lanes),
// followed by packed lower-triangular inverse into li.
__device__ __forceinline__ void chol_inv6_2(u64 a[21], u64 li[21]) {
    u64 invd[6], ninvd[6];
#pragma unroll
    for (int j = 0; j < 6; j++) {
        u64 d = a[j * (j + 1) / 2 + j];
#pragma unroll
        for (int t = 0; t < j; t++) {
            u64 v = a[j * (j + 1) / 2 + t];
            d = fma2(mul2(v, NEG1_2), v, d);     // d -= v*v (both lanes)
        }
        PF df; df.u = d;
        u64 inv = pack2(rsqrtf(df.f.x), rsqrtf(df.f.y));
        a[j * (j + 1) / 2 + j] = mul2(d, inv);   // sqrt(d) = d * rsqrt(d)
        invd[j] = inv;
        ninvd[j] = mul2(inv, NEG1_2);
#pragma unroll
        for (int i = j + 1; i < 6; i++) {
            u64 s = a[i * (i + 1) / 2 + j];
#pragma unroll
            for (int t = 0; t < j; t++)
                s = fma2(mul2(a[i * (i + 1) / 2 + t], NEG1_2),
                         a[j * (j + 1) / 2 + t], s);
            a[i * (i + 1) / 2 + j] = mul2(s, inv);
        }
    }
#pragma unroll
    for (int j = 0; j < 6; j++) {
        li[j * (j + 1) / 2 + j] = invd[j];
#pragma unroll
        for (int i = j + 1; i < 6; i++) {
            u64 s = 0ull;                         // (0.f, 0.f)
#pragma unroll
            for (int t = j; t < i; t++)
                s = fma2(a[i * (i + 1) / 2 + t], li[t * (t + 1) / 2 + j], s);
            li[i * (i + 1) / 2 + j] = mul2(s, ninvd[i]);  // -s * invd[i]
        }
    }
}

// Accumulate (SUB=false) or subtract (SUB=true) one padded row's horizontal
// k-window of products into the packed accumulators.
template <int K, int CS, bool SUB>
__device__ __forceinline__ void accum_row(
    const u64* __restrict__ s, int off,
    u64* __restrict__ SP, u64* __restrict__ SPP, float* __restrict__ Sxy) {
#pragma unroll
    for (int dx = 0; dx < K; dx++) {
        PF P[6], Pm[6];
#pragma unroll
        for (int c = 0; c < 6; c++) {
            P[c].u = s[c * CS + off + dx];
            Pm[c].u = SUB ? mul2(P[c].u, NEG1_2) : P[c].u;
        }
#pragma unroll
        for (int i = 0; i < 6; i++) SP[i] = add2(SP[i], Pm[i].u);
#pragma unroll
        for (int i = 0; i < 6; i++)
#pragma unroll
            for (int j = 0; j <= i; j++)
                SPP[i * (i + 1) / 2 + j] =
                    fma2(Pm[i].u, P[j].u, SPP[i * (i + 1) / 2 + j]);  // (xx, yy)
#pragma unroll
        for (int i = 0; i < 6; i++)
#pragma unroll
            for (int j = 0; j < 6; j++)
                Sxy[i * 6 + j] = fmaf(Pm[i].f.x, P[j].f.y, Sxy[i * 6 + j]);
    }
}

template <int K>
__device__ __forceinline__ float cca_epilogue(
    const u64* __restrict__ SP, const u64* __restrict__ SPP,
    const float* __restrict__ Sxy) {
    constexpr float ia = 1.0f / (float)(K * K);
    const u64 IA2  = pack2(ia, ia);
    const u64 EPS2 = pack2(EPSV, EPSV);

    PF M[6], Mn[6];
#pragma unroll
    for (int i = 0; i < 6; i++) {
        M[i].u  = mul2(SP[i], IA2);      // (mx, my)
        Mn[i].u = mul2(M[i].u, NEG1_2);
    }

    // A = SPP*ia - M_i*M_j (+eps on diag), packed (cxx | cyy)
    u64 A[21], LI[21];
#pragma unroll
    for (int i = 0; i < 6; i++)
#pragma unroll
        for (int j = 0; j <= i; j++) {
            int t = i * (i + 1) / 2 + j;
            u64 v = fma2(Mn[i].u, M[j].u, mul2(SPP[t], IA2));
            A[t] = (i == j) ? add2(v, EPS2) : v;
        }
    chol_inv6_2(A, LI);

    // cxy scalar (built after chol to shorten A's live range)
    float cxy[36];
#pragma unroll
    for (int i = 0; i < 6; i++)
#pragma unroll
        for (int j = 0; j < 6; j++)
            cxy[i * 6 + j] = fmaf(-M[i].f.x, M[j].f.y, Sxy[i * 6 + j] * ia);

    // diag_d = sum_{j<=d} sum_{k>=d} lxi[d][j] * cxy[j][k] * lyi[k][d]
    float acc = 0.0f;
#pragma unroll
    for (int d = 0; d < 6; d++) {
        float dv = 0.0f;
#pragma unroll
        for (int k = d; k < 6; k++) {
            float t = 0.0f;
#pragma unroll
            for (int j = 0; j <= d; j++) {
                PF l; l.u = LI[d * (d + 1) / 2 + j];
                t = fmaf(l.f.x, cxy[j * 6 + k], t);
            }
            PF r; r.u = LI[k * (k + 1) / 2 + d];
            dv = fmaf(t, r.f.y, dv);
        }
        acc += fabsf(dv);
    }
    return acc * (1.0f / 6.0f);
}

template <int R>
__global__ __launch_bounds__(TX * TYT, 1)
void cca_kernel(const float* __restrict__ x, const float* __restrict__ y,
                float* __restrict__ out, int ridx) {
    constexpr int K  = 2 * R + 1;
    constexpr int PW = TX + 2 * R;
    constexpr int PH = TILE_H + 2 * R;
    constexpr int CS = PH * PW;            // per-channel smem stride (pairs)

    extern __shared__ u64 sData[];         // [CH][PH][PW] packed (x, y)

    const int b  = blockIdx.z;
    const int x0 = blockIdx.x * TX;
    const int y0 = blockIdx.y * TILE_H;
    const int tid = threadIdx.y * TX + threadIdx.x;

    // Cooperative load with reflect padding resolved at load.
    for (int i = tid; i < CS; i += TX * TYT) {
        int ty = i / PW;
        int tx = i - ty * PW;
        int gy = refl(y0 + ty - R, HH);
        int gx = refl(x0 + tx - R, WW);
        long base = ((long)b * CH) * HH * WW + (long)gy * WW + gx;
#pragma unroll
        for (int c = 0; c < CH; c++) {
            long g = base + (long)c * HH * WW;
            PF p; p.f = make_float2(x[g], y[g]);
            sData[c * CS + i] = p.u;
        }
    }
    __syncthreads();

    u64 SP[6], SPP[21];
    float Sxy[36];
#pragma unroll
    for (int i = 0; i < 6; i++) SP[i] = 0ull;
#pragma unroll
    for (int i = 0; i < 21; i++) SPP[i] = 0ull;
#pragma unroll
    for (int i = 0; i < 36; i++) Sxy[i] = 0.f;

    const int tx = threadIdx.x;
    const int rb = threadIdx.y * NROWS;    // first output-local row for this thread
    const long outBase = (((long)b * HH + (y0 + rb)) * WW + (x0 + tx)) * 2 + ridx;

#pragma unroll 1
    for (int s = 0; s < NROWS; s++) {
        if (s == 0) {
#pragma unroll 1
            for (int p = 0; p < K; p++)
                accum_row<K, CS, false>(sData, (rb + p) * PW + tx, SP, SPP, Sxy);
        } else {
            accum_row<K, CS, true >(sData, (rb + s - 1) * PW + tx, SP, SPP, Sxy);
            accum_row<K, CS, false>(sData, (rb + s - 1 + K) * PW + tx, SP, SPP, Sxy);
        }
        out[outBase + (long)s * WW * 2] = cca_epilogue<K>(SP, SPP, Sxy);
    }
}

extern "C" void kernel_launch(void* const* d_in, const int* in_sizes, int n_in,
                              void* d_out, int out_size) {
    const float* x = (const float*)d_in[0];
    const float* y = (const float*)d_in[1];
    float* out = (float*)d_out;

    const size_t smem2 = sizeof(u64) * CH * (TILE_H + 4) * (TX + 4);  // 117,504 B
    const size_t smem4 = sizeof(u64) * CH * (TILE_H + 8) * (TX + 8);  // 138,240 B
    cudaFuncSetAttribute(cca_kernel<2>, cudaFuncAttributeMaxDynamicSharedMemorySize, (int)smem2);
    cudaFuncSetAttribute(cca_kernel<4>, cudaFuncAttributeMaxDynamicSharedMemorySize, (int)smem4);

    dim3 block(TX, TYT, 1);
    dim3 grid(WW / TX, HH / TILE_H, BATCH);

    cca_kernel<2><<<grid, block, smem2>>>(x, y, out, 0);
    cca_kernel<4><<<grid, block, smem4>>>(x, y, out, 1);
}